// round 12
// baseline (speedup 1.0000x reference)
#include <cuda_runtime.h>
#include <cstdint>

#define B_  256
#define T_  512
#define I_  64
#define H_  512

#define CLUSTER 8
#define NGROUP  16
#define BC      16
#define NT      1024

#define STRIPE_BYTES 2048
#define SRC_EXPECT   4096        // 2 stripes per source per step

// per-CTA xh scratch: [cta][t][col(64)][row(16)]
__device__ float g_xh[(size_t)(NGROUP * CLUSTER) * T_ * 64 * BC];

typedef unsigned long long ull;

// ---------------- helpers ----------------
__device__ __forceinline__ void ffma2(ull &d, ull a, ull b) {
    asm("fma.rn.f32x2 %0, %1, %2, %0;" : "+l"(d) : "l"(a), "l"(b));
}
__device__ __forceinline__ ull addf2(ull a, ull b) {
    ull d; asm("add.rn.f32x2 %0, %1, %2;" : "=l"(d) : "l"(a), "l"(b)); return d;
}
__device__ __forceinline__ ull dup2(float w) {
    ull r; asm("mov.b64 %0, {%1, %1};" : "=l"(r) : "f"(w)); return r;
}
__device__ __forceinline__ float2 unpack2(ull v) {
    float2 r; asm("mov.b64 {%0, %1}, %2;" : "=f"(r.x), "=f"(r.y) : "l"(v)); return r;
}
__device__ __forceinline__ float tanh_ap(float x) {
    float y; asm("tanh.approx.f32 %0, %1;" : "=f"(y) : "f"(x)); return y;
}
__device__ __forceinline__ void mbar_wait(uint32_t mbar, uint32_t parity) {
    asm volatile(
        "{\n\t.reg .pred P;\n\t"
        "WL_%=:\n\t"
        "mbarrier.try_wait.parity.acquire.cta.shared::cta.b64 P, [%0], %1, 0x989680;\n\t"
        "@P bra.uni WD_%=;\n\t"
        "bra.uni WL_%=;\n\t"
        "WD_%=:\n\t}"
        :: "r"(mbar), "r"(parity) : "memory");
}

// ---------------- SMEM layout (float offsets) ----------------
#define OFF_U   0                       // [512][64] W_hh slice      (131072 B)
#define OFF_Z   (H_ * 64)               // [2][512][16] hidden       ( 65536 B)
#define OFF_RED (OFF_Z + 2 * H_ * BC)   // 8192 fl = 32 KB, 8 slabs; Wxs alias
#define OFF_MB  (OFF_RED + 8192)        // 16 mbars (128 B)
#define SMEM_FLOATS (OFF_MB + 32)       // 57376 fl = 229504 B

// slab: 0..7, i: 0..7, slot: 0..63
#define RED(slab, i, slot) (((slab) * 8 + (i)) * 64 + (slot))

__global__ void __launch_bounds__(NT, 1) __cluster_dims__(CLUSTER, 1, 1)
rnn_fused(const float* __restrict__ x,
          const float* __restrict__ Wxh,
          const float* __restrict__ Whh,
          const float* __restrict__ bias,
          const float* __restrict__ fcw,
          const float* __restrict__ fcb,
          float* __restrict__ out) {
    extern __shared__ float sm[];
    float* U   = sm + OFF_U;
    float* z   = sm + OFF_Z;
    ull*  red  = (ull*)(sm + OFF_RED);
    float* Wxs = sm + OFF_RED;          // phase-0 alias
    float* x_ts = sm + OFF_Z;           // phase-0 alias (64 KB = z region)

    const uint32_t smem_u32 = (uint32_t)__cvta_generic_to_shared(sm);
    const uint32_t mb_base = smem_u32 + OFF_MB * 4;   // mbar[buf*8+src]

    const int tid  = threadIdx.x;
    const int cta  = blockIdx.x;
    const int rank = cta & 7;
    const int bg   = cta >> 3;
    const int jbase = rank * 64;
    const int b0 = bg * BC;
    const int wid = tid >> 5, lane = tid & 31;

    // init 16 mbars; pre-arm the 14 used (src != rank)
    if (tid < 16) {
        asm volatile("mbarrier.init.shared.b64 [%0], 1;"
                     :: "r"(mb_base + tid * 8) : "memory");
    }
    __syncthreads();
    if (tid < 16 && (tid & 7) != rank) {
        asm volatile("mbarrier.arrive.expect_tx.shared.b64 _, [%0], %1;"
                     :: "r"(mb_base + tid * 8), "r"(SRC_EXPECT) : "memory");
    }

    // stage U = W_hh[:, jbase..+64) as U[k][64]
    for (int i = tid; i < H_ * 16; i += NT) {
        int k = i >> 4, q = i & 15;
        *(float4*)&U[k * 64 + q * 4] =
            *(const float4*)&Whh[(size_t)k * H_ + jbase + q * 4];
    }
    // stage Wxs
    for (int i = tid; i < I_ * 16; i += NT) {
        int k = i >> 4, q = i & 15;
        *(float4*)&Wxs[k * 64 + q * 4] =
            *(const float4*)&Wxh[(size_t)k * H_ + jbase + q * 4];
    }
    __syncthreads();

    const int cg = lane & 7, rg = lane >> 3;

    // ===== phase 0: g_xh[cta] = x(own 16 rows) @ Wxs, layout [t][col][row] =====
    {
        const int pr  = tid & 15;          // stage: batch row
        const int pih = (tid >> 4) & 3;    // stage: i-quarter
        const int ptt = tid >> 6;          // stage: t in chunk (0..15)
        const int ptw = wid >> 1;          // compute: t in chunk (0..15)
        const int pcb = (wid & 1) * 32 + cg * 4;
        const int pr0 = rg * 4;

        for (int t0 = 0; t0 < T_; t0 += 16) {
            {   // stage x_ts[t][i][r] transposed (16 t x 64 i x 16 r = 64 KB)
                const float* xp = x + ((size_t)(b0 + pr) * T_ + t0 + ptt) * I_ + pih * 16;
                float4 v0 = *(const float4*)(xp);
                float4 v1 = *(const float4*)(xp + 4);
                float4 v2 = *(const float4*)(xp + 8);
                float4 v3 = *(const float4*)(xp + 12);
                float* xd = x_ts + (ptt * 64 + pih * 16) * 16 + pr;
                xd[0*16]=v0.x;  xd[1*16]=v0.y;  xd[2*16]=v0.z;  xd[3*16]=v0.w;
                xd[4*16]=v1.x;  xd[5*16]=v1.y;  xd[6*16]=v1.z;  xd[7*16]=v1.w;
                xd[8*16]=v2.x;  xd[9*16]=v2.y;  xd[10*16]=v2.z; xd[11*16]=v2.w;
                xd[12*16]=v3.x; xd[13*16]=v3.y; xd[14*16]=v3.z; xd[15*16]=v3.w;
            }
            __syncthreads();

            ull a0=0,a1=0,a2=0,a3=0,a4=0,a5=0,a6=0,a7=0;
            #pragma unroll 8
            for (int k = 0; k < I_; k++) {
                float4 w4 = *(const float4*)&Wxs[k * 64 + pcb];
                ulonglong2 h2 = *(const ulonglong2*)&x_ts[(ptw * 64 + k) * 16 + pr0];
                ull w0=dup2(w4.x), w1=dup2(w4.y), w2=dup2(w4.z), w3=dup2(w4.w);
                ffma2(a0,h2.x,w0); ffma2(a1,h2.y,w0);
                ffma2(a2,h2.x,w1); ffma2(a3,h2.y,w1);
                ffma2(a4,h2.x,w2); ffma2(a5,h2.y,w2);
                ffma2(a6,h2.x,w3); ffma2(a7,h2.y,w3);
            }
            float* gb = g_xh + ((size_t)cta * T_ + t0 + ptw) * 1024;
            float2 pA, pB;
            pA=unpack2(a0); pB=unpack2(a1);
            *(float4*)&gb[(pcb+0)*16 + pr0] = make_float4(pA.x,pA.y,pB.x,pB.y);
            pA=unpack2(a2); pB=unpack2(a3);
            *(float4*)&gb[(pcb+1)*16 + pr0] = make_float4(pA.x,pA.y,pB.x,pB.y);
            pA=unpack2(a4); pB=unpack2(a5);
            *(float4*)&gb[(pcb+2)*16 + pr0] = make_float4(pA.x,pA.y,pB.x,pB.y);
            pA=unpack2(a6); pB=unpack2(a7);
            *(float4*)&gb[(pcb+3)*16 + pr0] = make_float4(pA.x,pA.y,pB.x,pB.y);
            __syncthreads();
        }
    }

    // zero h buffer 0 (and buffer 1 region is overwritten before first read)
    for (int i = tid; i < H_ * BC / 4; i += NT)
        ((float4*)z)[i] = make_float4(0.f, 0.f, 0.f, 0.f);
    __syncthreads();
    asm volatile("barrier.cluster.arrive.aligned;" ::: "memory");
    asm volatile("barrier.cluster.wait.aligned;" ::: "memory");

    // ===== recurrence =====
    const int s  = wid >> 1;                   // 0..15
    const int ch = wid & 1;
    const int l  = (rank * 2 + s) & 15;        // logical k-slice (32 k's)
    const int src = (rank + (s >> 1)) & 7;     // source CTA of this slice
    const bool needwait = (s >= 2);
    const bool isS1 = (wid == 2 || wid == 3);
    const int cbase = ch * 32 + cg * 4;
    const int r0 = rg * 4;
    const int slot = ch * 32 + lane;           // 0..63
    const int zoff = l * 32 * 16;
    const float* Ub = U + l * 32 * 64;
    const float* gxb = g_xh + (size_t)cta * T_ * 1024 + cbase * 16 + r0;
    const float4 bj4 = *(const float4*)&bias[jbase + cbase];

    const uint32_t stripe_local = smem_u32 + OFF_Z * 4
                                + (uint32_t)(jbase + ch * 32) * 64;
    uint32_t dst_base = 0, rmb_map = 0;
    if (wid < 2 && lane < 7) {
        int c = (rank + 1 + lane) & 7;
        asm("mapa.shared::cluster.u32 %0, %1, %2;" : "=r"(dst_base) : "r"(stripe_local), "r"(c));
        asm("mapa.shared::cluster.u32 %0, %1, %2;" : "=r"(rmb_map) : "r"(mb_base), "r"(c));
    }
    const uint32_t ZBUFB = H_ * BC * 4;
    uint32_t par0 = 0, par1 = 0;

    for (int t = 0; t < T_; t++) {
        const int cur = t & 1, nxt = cur ^ 1;

        if (t >= 1) {
            if (needwait) {
                const uint32_t mb = mb_base + (uint32_t)(cur * 8 + src) * 8;
                mbar_wait(mb, cur ? par1 : par0);
                if (!(s & 1) && ch == 0 && lane == 0)
                    asm volatile("mbarrier.arrive.expect_tx.shared.b64 _, [%0], %1;"
                                 :: "r"(mb), "r"(SRC_EXPECT) : "memory");
                if (cur) par1 ^= 1; else par0 ^= 1;
            } else if (isS1) {
                asm volatile("bar.sync 1, 128;" ::: "memory");
            }
        }

        const float* zb = z + cur * (H_ * BC) + zoff;
        ull a0=0,a1=0,a2=0,a3=0,a4=0,a5=0,a6=0,a7=0;
        #pragma unroll 8
        for (int i = 0; i < 32; i++) {
            float4 w4 = *(const float4*)&Ub[i * 64 + cbase];
            ulonglong2 h2 = *(const ulonglong2*)&zb[i * 16 + r0];
            ull w0=dup2(w4.x), w1=dup2(w4.y), w2=dup2(w4.z), w3=dup2(w4.w);
            ffma2(a0,h2.x,w0); ffma2(a1,h2.y,w0);
            ffma2(a2,h2.x,w1); ffma2(a3,h2.y,w1);
            ffma2(a4,h2.x,w2); ffma2(a5,h2.y,w2);
            ffma2(a6,h2.x,w3); ffma2(a7,h2.y,w3);
        }

        // producers prefetch xh (latency covered by the reduction rounds)
        float4 xh0, xh1, xh2, xh3;
        if (wid < 2) {
            const float* gx = gxb + (size_t)t * 1024;
            xh0 = *(const float4*)(gx);
            xh1 = *(const float4*)(gx + 16);
            xh2 = *(const float4*)(gx + 32);
            xh3 = *(const float4*)(gx + 48);
        }

        // ===== reduction 16 -> 1 (4 syncthreads) =====
        if (s & 1) {                        // R1 write: odd s -> slab s>>1
            ull* w = red; int slab = s >> 1;
            w[RED(slab,0,slot)]=a0; w[RED(slab,1,slot)]=a1;
            w[RED(slab,2,slot)]=a2; w[RED(slab,3,slot)]=a3;
            w[RED(slab,4,slot)]=a4; w[RED(slab,5,slot)]=a5;
            w[RED(slab,6,slot)]=a6; w[RED(slab,7,slot)]=a7;
        }
        __syncthreads();                    // sync1
        if (!(s & 1)) {                     // R1 add: even s
            const ull* r_ = red; int slab = s >> 1;
            a0=addf2(a0,r_[RED(slab,0,slot)]); a1=addf2(a1,r_[RED(slab,1,slot)]);
            a2=addf2(a2,r_[RED(slab,2,slot)]); a3=addf2(a3,r_[RED(slab,3,slot)]);
            a4=addf2(a4,r_[RED(slab,4,slot)]); a5=addf2(a5,r_[RED(slab,5,slot)]);
            a6=addf2(a6,r_[RED(slab,6,slot)]); a7=addf2(a7,r_[RED(slab,7,slot)]);
        }
        __syncthreads();                    // sync2
        if (!(s & 1) && (s >> 1) >= 4) {    // R2 write: q4..7 -> slabs 0..3
            ull* w = red; int slab = (s >> 1) - 4;
            w[RED(slab,0,slot)]=a0; w[RED(slab,1,slot)]=a1;
            w[RED(slab,2,slot)]=a2; w[RED(slab,3,slot)]=a3;
            w[RED(slab,4,slot)]=a4; w[RED(slab,5,slot)]=a5;
            w[RED(slab,6,slot)]=a6; w[RED(slab,7,slot)]=a7;
        }
        __syncthreads();                    // sync3
        if (!(s & 1) && (s >> 1) < 4) {     // R2 add: q0..3
            const ull* r_ = red; int slab = s >> 1;
            a0=addf2(a0,r_[RED(slab,0,slot)]); a1=addf2(a1,r_[RED(slab,1,slot)]);
            a2=addf2(a2,r_[RED(slab,2,slot)]); a3=addf2(a3,r_[RED(slab,3,slot)]);
            a4=addf2(a4,r_[RED(slab,4,slot)]); a5=addf2(a5,r_[RED(slab,5,slot)]);
            a6=addf2(a6,r_[RED(slab,6,slot)]); a7=addf2(a7,r_[RED(slab,7,slot)]);
            int q = s >> 1;
            if (q >= 1) {                   // R3 write: q1..3 -> slabs 4..6
                ull* w = red; int slab = 3 + q;
                w[RED(slab,0,slot)]=a0; w[RED(slab,1,slot)]=a1;
                w[RED(slab,2,slot)]=a2; w[RED(slab,3,slot)]=a3;
                w[RED(slab,4,slot)]=a4; w[RED(slab,5,slot)]=a5;
                w[RED(slab,6,slot)]=a6; w[RED(slab,7,slot)]=a7;
            }
        }
        __syncthreads();                    // sync4

        if (wid < 2) {                      // q0: final adds + epilogue + push
            const ull* r_ = red;
            #pragma unroll
            for (int slab = 4; slab <= 6; slab++) {
                a0=addf2(a0,r_[RED(slab,0,slot)]); a1=addf2(a1,r_[RED(slab,1,slot)]);
                a2=addf2(a2,r_[RED(slab,2,slot)]); a3=addf2(a3,r_[RED(slab,3,slot)]);
                a4=addf2(a4,r_[RED(slab,4,slot)]); a5=addf2(a5,r_[RED(slab,5,slot)]);
                a6=addf2(a6,r_[RED(slab,6,slot)]); a7=addf2(a7,r_[RED(slab,7,slot)]);
            }

            float* dstl = z + nxt * (H_ * BC) + (jbase + cbase) * 16 + r0;
            float2 pA, pB; float4 o;
            pA=unpack2(a0); pB=unpack2(a1);
            o.x=tanh_ap(pA.x+xh0.x+bj4.x); o.y=tanh_ap(pA.y+xh0.y+bj4.x);
            o.z=tanh_ap(pB.x+xh0.z+bj4.x); o.w=tanh_ap(pB.y+xh0.w+bj4.x);
            *(float4*)&dstl[0 * 16] = o;
            pA=unpack2(a2); pB=unpack2(a3);
            o.x=tanh_ap(pA.x+xh1.x+bj4.y); o.y=tanh_ap(pA.y+xh1.y+bj4.y);
            o.z=tanh_ap(pB.x+xh1.z+bj4.y); o.w=tanh_ap(pB.y+xh1.w+bj4.y);
            *(float4*)&dstl[1 * 16] = o;
            pA=unpack2(a4); pB=unpack2(a5);
            o.x=tanh_ap(pA.x+xh2.x+bj4.z); o.y=tanh_ap(pA.y+xh2.y+bj4.z);
            o.z=tanh_ap(pB.x+xh2.z+bj4.z); o.w=tanh_ap(pB.y+xh2.w+bj4.z);
            *(float4*)&dstl[2 * 16] = o;
            pA=unpack2(a6); pB=unpack2(a7);
            o.x=tanh_ap(pA.x+xh3.x+bj4.w); o.y=tanh_ap(pA.y+xh3.y+bj4.w);
            o.z=tanh_ap(pB.x+xh3.z+bj4.w); o.w=tanh_ap(pB.y+xh3.w+bj4.w);
            *(float4*)&dstl[3 * 16] = o;

            __syncwarp();
            asm volatile("bar.sync 1, 128;" ::: "memory");   // pairs with s1 @ t+1
            if (lane < 7) {
                asm volatile("fence.proxy.async.shared::cta;" ::: "memory");
                const uint32_t woff = (uint32_t)nxt * ZBUFB;
                asm volatile(
                    "cp.async.bulk.shared::cluster.shared::cta.mbarrier::complete_tx::bytes "
                    "[%0], [%1], %2, [%3];"
                    :: "r"(dst_base + woff), "r"(stripe_local + woff),
                       "r"(STRIPE_BYTES),
                       "r"(rmb_map + (uint32_t)(nxt * 8 + rank) * 8)
                    : "memory");
            }
        }
    }

    // final drains: every waiting warp absorbs the t=511 push (buffer 0)
    if (needwait) {
        mbar_wait(mb_base + (uint32_t)src * 8, par0);
    } else if (isS1) {
        asm volatile("bar.sync 1, 128;" ::: "memory");
    }
    __syncthreads();

    // ===== epilogue: rank 0 computes out = h_final @ fc_w^T + fc_b =====
    if (rank == 0 && tid < 128) {
        const float* hf = z;                // final h in buffer 0
        const int r  = tid >> 3;
        const int sg = tid & 7;
        float p = 0.f;
        #pragma unroll 8
        for (int j = sg * 64; j < sg * 64 + 64; j++)
            p = fmaf(hf[j * 16 + r], fcw[j], p);
        p += __shfl_xor_sync(0xffffffffu, p, 4);
        p += __shfl_xor_sync(0xffffffffu, p, 2);
        p += __shfl_xor_sync(0xffffffffu, p, 1);
        if (sg == 0) out[b0 + r] = p + fcb[0];
    }
    asm volatile("barrier.cluster.arrive.aligned;" ::: "memory");
    asm volatile("barrier.cluster.wait.aligned;" ::: "memory");
}

// ================= launch =================
extern "C" void kernel_launch(void* const* d_in, const int* in_sizes, int n_in,
                              void* d_out, int out_size) {
    const float* x    = (const float*)d_in[0];
    const float* Wxh  = (const float*)d_in[1];
    const float* Whh  = (const float*)d_in[2];
    const float* bias = (const float*)d_in[3];
    const float* fcw  = (const float*)d_in[4];
    const float* fcb  = (const float*)d_in[5];
    float* out = (float*)d_out;

    const int smem = SMEM_FLOATS * 4;       // 229504 B
    cudaFuncSetAttribute(rnn_fused, cudaFuncAttributeMaxDynamicSharedMemorySize, smem);
    rnn_fused<<<NGROUP * CLUSTER, NT, smem>>>(x, Wxh, Whh, bias, fcw, fcb, out);
}